// round 6
// baseline (speedup 1.0000x reference)
#include <cuda_runtime.h>
#include <cuda_fp16.h>
#include <cuda_bf16.h>

#define N_NODES 100000
#define D_DIM   64
#define E_EDGES 1600000

#define SCAN_BLOCK 1024
#define N_SCAN_BLOCKS ((N_NODES + SCAN_BLOCK - 1) / SCAN_BLOCK)   // 98

// ---- device scratch (no cudaMalloc allowed; zero-initialized at load) ----
__device__ float  g_adst[N_NODES];          // h[i].w_dst + bias
__device__ float2 g_spack[N_NODES];         // (h[i].w_src, dnorm[i])
__device__ int    g_counts[N_NODES];        // in-degree histogram
                                            // INVARIANT: zero on kernel_launch entry
                                            // (re-zeroed by add_base_kernel each call)
__device__ int    g_offsets[N_NODES + 1];   // CSR row offsets
__device__ int    g_cursor[N_NODES];        // scatter cursors
__device__ int    g_blocksums[N_SCAN_BLOCKS];
__device__ int    g_edge_src[E_EDGES];      // CSR column (src node) list
__device__ __half g_hhalf[N_NODES * D_DIM]; // fp16 mirror of h

__device__ __forceinline__ float fast_tanh(float x) {
    float r;
    asm("tanh.approx.f32 %0, %1;" : "=f"(r) : "f"(x));
    return r;
}

// ---------------------------------------------------------------------------
// K1: per-node gate partials (warp per node) + fp16 mirror + FUSED histogram.
// ---------------------------------------------------------------------------
__global__ void node_dots_hist_kernel(const float* __restrict__ h,
                                      const float* __restrict__ dnorm,
                                      const float* __restrict__ gate_w,
                                      const float* __restrict__ gate_b,
                                      const int*   __restrict__ dst)
{
    int tid  = blockIdx.x * blockDim.x + threadIdx.x;
    int warp = tid >> 5;
    int lane = tid & 31;

    if (tid < E_EDGES)
        atomicAdd(&g_counts[dst[tid]], 1);

    if (warp >= N_NODES) return;

    float2 hv = *reinterpret_cast<const float2*>(h + (long long)warp * D_DIM + lane * 2);

    *reinterpret_cast<__half2*>(g_hhalf + (long long)warp * D_DIM + lane * 2) =
        __floats2half2_rn(hv.x, hv.y);

    float2 wd = *reinterpret_cast<const float2*>(gate_w + lane * 2);
    float2 ws = *reinterpret_cast<const float2*>(gate_w + D_DIM + lane * 2);

    float pd = hv.x * wd.x + hv.y * wd.y;
    float ps = hv.x * ws.x + hv.y * ws.y;

    #pragma unroll
    for (int off = 16; off > 0; off >>= 1) {
        pd += __shfl_xor_sync(0xFFFFFFFFu, pd, off);
        ps += __shfl_xor_sync(0xFFFFFFFFu, ps, off);
    }

    if (lane == 0) {
        g_adst[warp]  = pd + gate_b[0];
        g_spack[warp] = make_float2(ps, dnorm[warp]);
    }
}

// ---------------------------------------------------------------------------
// K2: per-block exclusive scan (Hillis-Steele in smem), writes block sums
// ---------------------------------------------------------------------------
__global__ void scan_blocks_kernel()
{
    __shared__ int sdata[SCAN_BLOCK];
    int tid = threadIdx.x;
    int i   = blockIdx.x * SCAN_BLOCK + tid;
    int v   = (i < N_NODES) ? g_counts[i] : 0;
    sdata[tid] = v;
    __syncthreads();

    #pragma unroll
    for (int off = 1; off < SCAN_BLOCK; off <<= 1) {
        int t = (tid >= off) ? sdata[tid - off] : 0;
        __syncthreads();
        sdata[tid] += t;
        __syncthreads();
    }

    if (i < N_NODES) g_offsets[i] = sdata[tid] - v;
    if (tid == SCAN_BLOCK - 1) g_blocksums[blockIdx.x] = sdata[tid];
}

// ---------------------------------------------------------------------------
// K3: add block bases, init cursors, re-zero counts, fix offsets[N].
// ---------------------------------------------------------------------------
__global__ void add_base_kernel()
{
    __shared__ int ssum[128];
    int tid = threadIdx.x;
    if (tid < 128)
        ssum[tid] = (tid < N_SCAN_BLOCKS) ? g_blocksums[tid] : 0;
    __syncthreads();

    #pragma unroll
    for (int off = 1; off < 128; off <<= 1) {
        int t = 0;
        if (tid < 128 && tid >= off) t = ssum[tid - off];
        __syncthreads();
        if (tid < 128) ssum[tid] += t;
        __syncthreads();
    }
    int base = (blockIdx.x == 0) ? 0 : ssum[blockIdx.x - 1];

    int i = blockIdx.x * SCAN_BLOCK + tid;
    if (i < N_NODES) {
        int val = g_offsets[i] + base;
        g_offsets[i] = val;
        g_cursor[i]  = val;
        g_counts[i]  = 0;
    }
    if (blockIdx.x == 0 && tid == 0) g_offsets[N_NODES] = E_EDGES;
}

// ---------------------------------------------------------------------------
// K4: scatter src ids into CSR. 8 edges/thread (two int4 loads) so 8
// independent atomic+store chains are in flight per thread.
// No coef math here (R5 showed that regresses — coef belongs in the gather
// where adst[d]/dnorm[d] are warp-uniform).
// ---------------------------------------------------------------------------
__global__ void csr_scatter_kernel(const int* __restrict__ src,
                                   const int* __restrict__ dst)
{
    int t = blockIdx.x * blockDim.x + threadIdx.x;
    if (t >= E_EDGES / 8) return;

    const int4* s4p = reinterpret_cast<const int4*>(src) + t * 2;
    const int4* d4p = reinterpret_cast<const int4*>(dst) + t * 2;
    int4 sa = s4p[0], sb = s4p[1];
    int4 da = d4p[0], db = d4p[1];

    int p0 = atomicAdd(&g_cursor[da.x], 1);
    int p1 = atomicAdd(&g_cursor[da.y], 1);
    int p2 = atomicAdd(&g_cursor[da.z], 1);
    int p3 = atomicAdd(&g_cursor[da.w], 1);
    int p4 = atomicAdd(&g_cursor[db.x], 1);
    int p5 = atomicAdd(&g_cursor[db.y], 1);
    int p6 = atomicAdd(&g_cursor[db.z], 1);
    int p7 = atomicAdd(&g_cursor[db.w], 1);

    g_edge_src[p0] = sa.x;
    g_edge_src[p1] = sa.y;
    g_edge_src[p2] = sa.z;
    g_edge_src[p3] = sa.w;
    g_edge_src[p4] = sb.x;
    g_edge_src[p5] = sb.y;
    g_edge_src[p6] = sb.z;
    g_edge_src[p7] = sb.w;
}

// ---------------------------------------------------------------------------
// K5: gather-accumulate. One warp per dst node, fp16 h rows, no atomics.
// Per edge: one 8B random gather (asrc,dnorm packed) + one 128B fp16 row.
// ---------------------------------------------------------------------------
__global__ void gather_kernel(const float* __restrict__ dnorm,
                              float* __restrict__ out)
{
    int tid  = blockIdx.x * blockDim.x + threadIdx.x;
    int d    = tid >> 5;
    int lane = tid & 31;
    if (d >= N_NODES) return;

    int beg = g_offsets[d];
    int end = g_offsets[d + 1];

    float adst_d = g_adst[d];
    float dnd    = dnorm[d];

    float accx = 0.f, accy = 0.f;
    const __half* __restrict__ hh = g_hhalf;

    for (int base = beg; base < end; base += 32) {
        int idx = base + lane;
        int s = 0;
        float coef = 0.f;
        if (idx < end) {
            s = g_edge_src[idx];
            float2 sp = g_spack[s];
            coef = fast_tanh(adst_d + sp.x) * dnd * sp.y;
        }
        int cnt = end - base;
        if (cnt > 32) cnt = 32;

        int j = 0;
        for (; j + 4 <= cnt; j += 4) {
            int   s0 = __shfl_sync(0xFFFFFFFFu, s, j);
            int   s1 = __shfl_sync(0xFFFFFFFFu, s, j + 1);
            int   s2 = __shfl_sync(0xFFFFFFFFu, s, j + 2);
            int   s3 = __shfl_sync(0xFFFFFFFFu, s, j + 3);
            float c0 = __shfl_sync(0xFFFFFFFFu, coef, j);
            float c1 = __shfl_sync(0xFFFFFFFFu, coef, j + 1);
            float c2 = __shfl_sync(0xFFFFFFFFu, coef, j + 2);
            float c3 = __shfl_sync(0xFFFFFFFFu, coef, j + 3);
            __half2 a0 = *reinterpret_cast<const __half2*>(hh + (long long)s0 * D_DIM + lane * 2);
            __half2 a1 = *reinterpret_cast<const __half2*>(hh + (long long)s1 * D_DIM + lane * 2);
            __half2 a2 = *reinterpret_cast<const __half2*>(hh + (long long)s2 * D_DIM + lane * 2);
            __half2 a3 = *reinterpret_cast<const __half2*>(hh + (long long)s3 * D_DIM + lane * 2);
            float2 f0 = __half22float2(a0);
            float2 f1 = __half22float2(a1);
            float2 f2 = __half22float2(a2);
            float2 f3 = __half22float2(a3);
            accx = fmaf(c0, f0.x, accx); accy = fmaf(c0, f0.y, accy);
            accx = fmaf(c1, f1.x, accx); accy = fmaf(c1, f1.y, accy);
            accx = fmaf(c2, f2.x, accx); accy = fmaf(c2, f2.y, accy);
            accx = fmaf(c3, f3.x, accx); accy = fmaf(c3, f3.y, accy);
        }
        for (; j < cnt; j++) {
            int   sj = __shfl_sync(0xFFFFFFFFu, s, j);
            float cj = __shfl_sync(0xFFFFFFFFu, coef, j);
            __half2 av = *reinterpret_cast<const __half2*>(hh + (long long)sj * D_DIM + lane * 2);
            float2 fv = __half22float2(av);
            accx = fmaf(cj, fv.x, accx);
            accy = fmaf(cj, fv.y, accy);
        }
    }

    *reinterpret_cast<float2*>(out + (long long)d * D_DIM + lane * 2) =
        make_float2(accx, accy);
}

// ---------------------------------------------------------------------------
// Launch (5 kernels)
// ---------------------------------------------------------------------------
extern "C" void kernel_launch(void* const* d_in, const int* in_sizes, int n_in,
                              void* d_out, int out_size)
{
    const float* h      = (const float*)d_in[0];   // (N, 64)
    const float* dnorm  = (const float*)d_in[1];   // (N,)
    const float* gate_w = (const float*)d_in[2];   // (1, 128)
    const float* gate_b = (const float*)d_in[3];   // (1,)
    const int*   src    = (const int*)  d_in[4];   // (E,)
    const int*   dst    = (const int*)  d_in[5];   // (E,)
    float* out = (float*)d_out;                    // (N, 64) float32

    {
        long long total = (long long)N_NODES * 32;
        int blocks = (int)((total + 255) / 256);
        node_dots_hist_kernel<<<blocks, 256>>>(h, dnorm, gate_w, gate_b, dst);
    }
    scan_blocks_kernel<<<N_SCAN_BLOCKS, SCAN_BLOCK>>>();
    add_base_kernel<<<N_SCAN_BLOCKS, SCAN_BLOCK>>>();
    {
        int threads = 256;
        int work = E_EDGES / 8;                    // 200000
        csr_scatter_kernel<<<(work + threads - 1) / threads, threads>>>(src, dst);
    }
    {
        long long total = (long long)N_NODES * 32;
        int blocks = (int)((total + 255) / 256);
        gather_kernel<<<blocks, 256>>>(dnorm, out);
    }
}

// round 7
// speedup vs baseline: 1.4323x; 1.4323x over previous
#include <cuda_runtime.h>
#include <cuda_fp16.h>
#include <cuda_bf16.h>

#define N_NODES 100000
#define D_DIM   64
#define E_EDGES 1600000

#define SCAN_BLOCK 1024
#define N_SCAN_BLOCKS ((N_NODES + SCAN_BLOCK - 1) / SCAN_BLOCK)   // 98

// ---- device scratch (no cudaMalloc allowed; zero-initialized at load) ----
__device__ float  g_adst[N_NODES];          // h[i].w_dst + bias
__device__ float2 g_spack[N_NODES];         // (h[i].w_src, dnorm[i])
__device__ int    g_counts[N_NODES];        // in-degree histogram
                                            // INVARIANT: zero on kernel_launch entry
                                            // (re-zeroed by add_base_kernel each call)
__device__ int    g_offsets[N_NODES + 1];   // CSR row offsets
__device__ int    g_rank[E_EDGES];          // edge rank within its dst bucket
__device__ int    g_blocksums[N_SCAN_BLOCKS];
__device__ int    g_edge_src[E_EDGES];      // CSR column (src node) list
__device__ __half g_hhalf[N_NODES * D_DIM]; // fp16 mirror of h

__device__ __forceinline__ float fast_tanh(float x) {
    float r;
    asm("tanh.approx.f32 %0, %1;" : "=f"(r) : "f"(x));
    return r;
}

// ---------------------------------------------------------------------------
// K1: per-node gate partials (warp per node) + fp16 mirror + FUSED histogram.
// The histogram atomicAdd's return value IS the edge's rank within its dst
// bucket — save it so the CSR scatter needs no atomics at all.
// ---------------------------------------------------------------------------
__global__ void node_dots_hist_kernel(const float* __restrict__ h,
                                      const float* __restrict__ dnorm,
                                      const float* __restrict__ gate_w,
                                      const float* __restrict__ gate_b,
                                      const int*   __restrict__ dst)
{
    int tid  = blockIdx.x * blockDim.x + threadIdx.x;
    int warp = tid >> 5;
    int lane = tid & 31;

    if (tid < E_EDGES)
        g_rank[tid] = atomicAdd(&g_counts[dst[tid]], 1);

    if (warp >= N_NODES) return;

    float2 hv = *reinterpret_cast<const float2*>(h + (long long)warp * D_DIM + lane * 2);

    *reinterpret_cast<__half2*>(g_hhalf + (long long)warp * D_DIM + lane * 2) =
        __floats2half2_rn(hv.x, hv.y);

    float2 wd = *reinterpret_cast<const float2*>(gate_w + lane * 2);
    float2 ws = *reinterpret_cast<const float2*>(gate_w + D_DIM + lane * 2);

    float pd = hv.x * wd.x + hv.y * wd.y;
    float ps = hv.x * ws.x + hv.y * ws.y;

    #pragma unroll
    for (int off = 16; off > 0; off >>= 1) {
        pd += __shfl_xor_sync(0xFFFFFFFFu, pd, off);
        ps += __shfl_xor_sync(0xFFFFFFFFu, ps, off);
    }

    if (lane == 0) {
        g_adst[warp]  = pd + gate_b[0];
        g_spack[warp] = make_float2(ps, dnorm[warp]);
    }
}

// ---------------------------------------------------------------------------
// K2: per-block exclusive scan (Hillis-Steele in smem), writes block sums
// ---------------------------------------------------------------------------
__global__ void scan_blocks_kernel()
{
    __shared__ int sdata[SCAN_BLOCK];
    int tid = threadIdx.x;
    int i   = blockIdx.x * SCAN_BLOCK + tid;
    int v   = (i < N_NODES) ? g_counts[i] : 0;
    sdata[tid] = v;
    __syncthreads();

    #pragma unroll
    for (int off = 1; off < SCAN_BLOCK; off <<= 1) {
        int t = (tid >= off) ? sdata[tid - off] : 0;
        __syncthreads();
        sdata[tid] += t;
        __syncthreads();
    }

    if (i < N_NODES) g_offsets[i] = sdata[tid] - v;
    if (tid == SCAN_BLOCK - 1) g_blocksums[blockIdx.x] = sdata[tid];
}

// ---------------------------------------------------------------------------
// K3: add block bases, re-zero counts, fix offsets[N]. (No cursors needed.)
// ---------------------------------------------------------------------------
__global__ void add_base_kernel()
{
    __shared__ int ssum[128];
    int tid = threadIdx.x;
    if (tid < 128)
        ssum[tid] = (tid < N_SCAN_BLOCKS) ? g_blocksums[tid] : 0;
    __syncthreads();

    #pragma unroll
    for (int off = 1; off < 128; off <<= 1) {
        int t = 0;
        if (tid < 128 && tid >= off) t = ssum[tid - off];
        __syncthreads();
        if (tid < 128) ssum[tid] += t;
        __syncthreads();
    }
    int base = (blockIdx.x == 0) ? 0 : ssum[blockIdx.x - 1];

    int i = blockIdx.x * SCAN_BLOCK + tid;
    if (i < N_NODES) {
        g_offsets[i] = g_offsets[i] + base;
        g_counts[i]  = 0;          // restore K1's invariant for next replay
    }
    if (blockIdx.x == 0 && tid == 0) g_offsets[N_NODES] = E_EDGES;
}

// ---------------------------------------------------------------------------
// K4: ATOMIC-FREE CSR scatter. pos = offsets[dst[e]] + rank[e].
// 4 edges/thread, int4 coalesced reads; per edge one random 4B gather
// (offsets) + one fire-and-forget scattered 4B store.
// ---------------------------------------------------------------------------
__global__ void csr_scatter_kernel(const int* __restrict__ src,
                                   const int* __restrict__ dst)
{
    int t = blockIdx.x * blockDim.x + threadIdx.x;
    if (t >= E_EDGES / 4) return;

    int4 s4 = reinterpret_cast<const int4*>(src)[t];
    int4 d4 = reinterpret_cast<const int4*>(dst)[t];
    int4 r4 = reinterpret_cast<const int4*>(g_rank)[t];

    int o0 = g_offsets[d4.x];
    int o1 = g_offsets[d4.y];
    int o2 = g_offsets[d4.z];
    int o3 = g_offsets[d4.w];

    g_edge_src[o0 + r4.x] = s4.x;
    g_edge_src[o1 + r4.y] = s4.y;
    g_edge_src[o2 + r4.z] = s4.z;
    g_edge_src[o3 + r4.w] = s4.w;
}

// ---------------------------------------------------------------------------
// K5: gather-accumulate. One warp per dst node, fp16 h rows, no atomics.
// ---------------------------------------------------------------------------
__global__ void gather_kernel(const float* __restrict__ dnorm,
                              float* __restrict__ out)
{
    int tid  = blockIdx.x * blockDim.x + threadIdx.x;
    int d    = tid >> 5;
    int lane = tid & 31;
    if (d >= N_NODES) return;

    int beg = g_offsets[d];
    int end = g_offsets[d + 1];

    float adst_d = g_adst[d];
    float dnd    = dnorm[d];

    float accx = 0.f, accy = 0.f;
    const __half* __restrict__ hh = g_hhalf;

    for (int base = beg; base < end; base += 32) {
        int idx = base + lane;
        int s = 0;
        float coef = 0.f;
        if (idx < end) {
            s = g_edge_src[idx];
            float2 sp = g_spack[s];
            coef = fast_tanh(adst_d + sp.x) * dnd * sp.y;
        }
        int cnt = end - base;
        if (cnt > 32) cnt = 32;

        int j = 0;
        for (; j + 4 <= cnt; j += 4) {
            int   s0 = __shfl_sync(0xFFFFFFFFu, s, j);
            int   s1 = __shfl_sync(0xFFFFFFFFu, s, j + 1);
            int   s2 = __shfl_sync(0xFFFFFFFFu, s, j + 2);
            int   s3 = __shfl_sync(0xFFFFFFFFu, s, j + 3);
            float c0 = __shfl_sync(0xFFFFFFFFu, coef, j);
            float c1 = __shfl_sync(0xFFFFFFFFu, coef, j + 1);
            float c2 = __shfl_sync(0xFFFFFFFFu, coef, j + 2);
            float c3 = __shfl_sync(0xFFFFFFFFu, coef, j + 3);
            __half2 a0 = *reinterpret_cast<const __half2*>(hh + (long long)s0 * D_DIM + lane * 2);
            __half2 a1 = *reinterpret_cast<const __half2*>(hh + (long long)s1 * D_DIM + lane * 2);
            __half2 a2 = *reinterpret_cast<const __half2*>(hh + (long long)s2 * D_DIM + lane * 2);
            __half2 a3 = *reinterpret_cast<const __half2*>(hh + (long long)s3 * D_DIM + lane * 2);
            float2 f0 = __half22float2(a0);
            float2 f1 = __half22float2(a1);
            float2 f2 = __half22float2(a2);
            float2 f3 = __half22float2(a3);
            accx = fmaf(c0, f0.x, accx); accy = fmaf(c0, f0.y, accy);
            accx = fmaf(c1, f1.x, accx); accy = fmaf(c1, f1.y, accy);
            accx = fmaf(c2, f2.x, accx); accy = fmaf(c2, f2.y, accy);
            accx = fmaf(c3, f3.x, accx); accy = fmaf(c3, f3.y, accy);
        }
        for (; j < cnt; j++) {
            int   sj = __shfl_sync(0xFFFFFFFFu, s, j);
            float cj = __shfl_sync(0xFFFFFFFFu, coef, j);
            __half2 av = *reinterpret_cast<const __half2*>(hh + (long long)sj * D_DIM + lane * 2);
            float2 fv = __half22float2(av);
            accx = fmaf(cj, fv.x, accx);
            accy = fmaf(cj, fv.y, accy);
        }
    }

    *reinterpret_cast<float2*>(out + (long long)d * D_DIM + lane * 2) =
        make_float2(accx, accy);
}

// ---------------------------------------------------------------------------
// Launch (5 kernels)
// ---------------------------------------------------------------------------
extern "C" void kernel_launch(void* const* d_in, const int* in_sizes, int n_in,
                              void* d_out, int out_size)
{
    const float* h      = (const float*)d_in[0];   // (N, 64)
    const float* dnorm  = (const float*)d_in[1];   // (N,)
    const float* gate_w = (const float*)d_in[2];   // (1, 128)
    const float* gate_b = (const float*)d_in[3];   // (1,)
    const int*   src    = (const int*)  d_in[4];   // (E,)
    const int*   dst    = (const int*)  d_in[5];   // (E,)
    float* out = (float*)d_out;                    // (N, 64) float32

    {
        long long total = (long long)N_NODES * 32;
        int blocks = (int)((total + 255) / 256);
        node_dots_hist_kernel<<<blocks, 256>>>(h, dnorm, gate_w, gate_b, dst);
    }
    scan_blocks_kernel<<<N_SCAN_BLOCKS, SCAN_BLOCK>>>();
    add_base_kernel<<<N_SCAN_BLOCKS, SCAN_BLOCK>>>();
    {
        int threads = 256;
        int work = E_EDGES / 4;                    // 400000
        csr_scatter_kernel<<<(work + threads - 1) / threads, threads>>>(src, dst);
    }
    {
        long long total = (long long)N_NODES * 32;
        int blocks = (int)((total + 255) / 256);
        gather_kernel<<<blocks, 256>>>(dnorm, out);
    }
}